// round 17
// baseline (speedup 1.0000x reference)
#include <cuda_runtime.h>
#include <cuda_fp16.h>
#include <cstdint>
#include <math.h>

// ================= scratch =================
__device__ __half g_x_h[4096 * 2048];
__device__ __half g_att_h[4096 * 2048];
__device__ __half g_Wq_h[6144 * 2048];   // WqkvT [n][k]
__device__ __half g_Wo_h[2048 * 2048];   // WoT
__device__ __half g_qh[4096 * 2048];     // Q (1/sqrt(128) folded)
__device__ __half g_kh[4096 * 2048];
__device__ __half g_vth[4096 * 2048];    // V^T per head [bh][d][s]
__device__ float2 g_rope[2048 * 64];

// ================= helpers =================
__device__ __forceinline__ uint32_t smem_u32(const void* p) {
    uint32_t a;
    asm("{ .reg .u64 t; cvta.to.shared.u64 t, %1; cvt.u32.u64 %0, t; }" : "=r"(a) : "l"(p));
    return a;
}
__device__ __forceinline__ void ldsm4(uint32_t (&r)[4], uint32_t addr) {
    asm volatile("ldmatrix.sync.aligned.m8n8.x4.shared.b16 {%0,%1,%2,%3}, [%4];"
        : "=r"(r[0]), "=r"(r[1]), "=r"(r[2]), "=r"(r[3]) : "r"(addr));
}
__device__ __forceinline__ void mma16816(float* c, const uint32_t* a, const uint32_t* b) {
    asm volatile("mma.sync.aligned.m16n8k16.row.col.f32.f16.f16.f32 "
        "{%0,%1,%2,%3}, {%4,%5,%6,%7}, {%8,%9}, {%0,%1,%2,%3};"
        : "+f"(c[0]), "+f"(c[1]), "+f"(c[2]), "+f"(c[3])
        : "r"(a[0]), "r"(a[1]), "r"(a[2]), "r"(a[3]), "r"(b[0]), "r"(b[1]));
}
__device__ __forceinline__ void cp16(uint32_t sa, const void* g) {
    asm volatile("cp.async.cg.shared.global [%0], [%1], 16;" :: "r"(sa), "l"(g));
}
#define CP_COMMIT() asm volatile("cp.async.commit_group;" ::: "memory")
#define CP_WAIT0()  asm volatile("cp.async.wait_group 0;" ::: "memory")
__device__ __forceinline__ uint32_t h2_bits(__half2 v) {
    return *reinterpret_cast<uint32_t*>(&v);
}

// ================= prep kernels =================
__global__ void convert_h(const float* __restrict__ in, __half* __restrict__ hi, int n) {
    int i = blockIdx.x * blockDim.x + threadIdx.x;
    if (i < n) hi[i] = __float2half(in[i]);
}

__global__ void rope_table_kernel()
{
    const int idx = blockIdx.x * blockDim.x + threadIdx.x;
    const int j = idx & 63;
    const int s = idx >> 6;
    const float theta = 1.0f / powf(10000.0f, (float)(2 * j) / 128.0f);
    float sn, cs;
    sincosf((float)s * theta, &sn, &cs);
    g_rope[idx] = make_float2(cs, sn);
}

__global__ void transpose_h(const float* __restrict__ W, __half* __restrict__ Thi,
                            int K, int N) {
    __shared__ float s[32][33];
    int n0 = blockIdx.x * 32, k0 = blockIdx.y * 32;
    int tx = threadIdx.x, ty = threadIdx.y;
#pragma unroll
    for (int j = 0; j < 32; j += 8)
        s[ty + j][tx] = W[(size_t)(k0 + ty + j) * N + n0 + tx];
    __syncthreads();
#pragma unroll
    for (int j = 0; j < 32; j += 8) {
        size_t o = (size_t)(n0 + ty + j) * K + k0 + tx;
        Thi[o] = __float2half(s[tx][ty + j]);
    }
}

// ================= fp16 GEMM mainloop: 128x256 tile, warp 64x64 =================
#define G2_A   0
#define G2_B   10240
#define G2_STG 30720
#define GW_SMEM (2 * G2_STG)
#define GQ_SMEM 65536

#define FP16_MAINLOOP256(Ah, Bh)                                                    \
    float acc[4][8][4];                                                             \
    _Pragma("unroll") for (int i = 0; i < 4; i++)                                   \
    _Pragma("unroll") for (int j = 0; j < 8; j++)                                   \
    _Pragma("unroll") for (int k = 0; k < 4; k++) acc[i][j][k] = 0.0f;              \
    const uint32_t sb0 = smem_u32(smem);                                            \
    const uint32_t aOff = (uint32_t)((wm * 64 + (lane & 15)) * 80 + ((lane >> 4) << 4)); \
    const uint32_t bOff = (uint32_t)((wn * 64 + (lane & 7) + ((lane >> 4) << 3)) * 80    \
                                     + (((lane >> 3) & 1) << 4));                   \
    auto load = [&](int kc, int st) {                                               \
        const uint32_t base = sb0 + (uint32_t)(st * G2_STG);                        \
        _Pragma("unroll")                                                           \
        for (int t = 0; t < 2; t++) {                                               \
            const int i = tid + t * 256;                                            \
            const int r = i >> 2;                                                   \
            const uint32_t o = (uint32_t)(r * 80 + (i & 3) * 16);                   \
            cp16(base + G2_A + o, Ah + (size_t)(bm + r) * 2048 + kc + (i & 3) * 8); \
        }                                                                           \
        _Pragma("unroll")                                                           \
        for (int t = 0; t < 4; t++) {                                               \
            const int i = tid + t * 256;                                            \
            const int r = i >> 2;                                                   \
            const uint32_t o = (uint32_t)(r * 80 + (i & 3) * 16);                   \
            cp16(base + G2_B + o, Bh + (size_t)(bn + r) * 2048 + kc + (i & 3) * 8); \
        }                                                                           \
    };                                                                              \
    load(0, 0);                                                                     \
    CP_COMMIT();                                                                    \
    for (int c = 0; c < 64; c++) {                                                  \
        CP_WAIT0();                                                                 \
        __syncthreads();                                                            \
        if (c + 1 < 64) {                                                           \
            load((c + 1) * 32, (c + 1) & 1);                                        \
            CP_COMMIT();                                                            \
        }                                                                           \
        const uint32_t sb = sb0 + (uint32_t)((c & 1) * G2_STG);                     \
        _Pragma("unroll")                                                           \
        for (int ks = 0; ks < 2; ks++) {                                            \
            const uint32_t ko = (uint32_t)(ks * 32);                                \
            uint32_t a0[4][4], b0[4][4];                                            \
            _Pragma("unroll") for (int mi = 0; mi < 4; mi++)                        \
                ldsm4(a0[mi], sb + G2_A + aOff + mi * 1280 + ko);                   \
            _Pragma("unroll") for (int nj = 0; nj < 4; nj++)                        \
                ldsm4(b0[nj], sb + G2_B + bOff + nj * 1280 + ko);                   \
            _Pragma("unroll") for (int mi = 0; mi < 4; mi++)                        \
            _Pragma("unroll") for (int ni = 0; ni < 8; ni++)                        \
                mma16816(acc[mi][ni], a0[mi], &b0[ni >> 1][(ni & 1) * 2]);          \
        }                                                                           \
    }

// ================= QKV GEMM + fused RoPE epilogue (tile spans 2 heads) =================
__global__ __launch_bounds__(256) void gemm_qkv_rope(
    const __half* __restrict__ Ah, const __half* __restrict__ Bh,
    const float* __restrict__ bias)
{
    extern __shared__ char smem[];
    const int tid = threadIdx.x;
    const int lane = tid & 31;
    const int wid = tid >> 5;
    const int wm = wid & 1;
    const int wn = wid >> 1;
    const int bm = blockIdx.y * 128;
    const int bn = blockIdx.x * 256;

    FP16_MAINLOOP256(Ah, Bh)

    __syncthreads();

    const int seg    = bn >> 11;          // 0=Q 1=K 2=V (tile never crosses seg: 2048%256==0)
    const int head0  = (bn & 2047) >> 7;  // first of the two heads in this tile
    const int bidx   = bm >> 11;
    const int s_base = bm & 2047;

    __half* sh = (__half*)smem;           // 2 heads x [128 x 128] fp16 = 64 KB

    const int rl = wm * 64 + (lane >> 2);
    const int cb = wn * 64 + (lane & 3) * 2;
    const float qscale = 0.08838834764831845f;

#pragma unroll
    for (int mi = 0; mi < 4; mi++) {
#pragma unroll
        for (int ni = 0; ni < 8; ni++) {
            const int c = cb + ni * 8;          // 0..255
            const int hsel = c >> 7;
            const int cl = c & 127;
            const int ho = hsel * 16384;
            const float b0 = bias[bn + c], b1 = bias[bn + c + 1];
            float v0 = acc[mi][ni][0] + b0, v1 = acc[mi][ni][1] + b1;
            float w0 = acc[mi][ni][2] + b0, w1 = acc[mi][ni][3] + b1;
            const int r0 = rl + mi * 16, r1 = r0 + 8;
            if (seg < 2) {
                const int j = cl >> 1;
                const float sc = (seg == 0) ? qscale : 1.0f;
                const float2 t0 = g_rope[(s_base + r0) * 64 + j];
                const float2 t1 = g_rope[(s_base + r1) * 64 + j];
                sh[ho + r0 * 128 + j]      = __float2half((v0 * t0.x - v1 * t0.y) * sc);
                sh[ho + r0 * 128 + j + 64] = __float2half((v0 * t0.y + v1 * t0.x) * sc);
                sh[ho + r1 * 128 + j]      = __float2half((w0 * t1.x - w1 * t1.y) * sc);
                sh[ho + r1 * 128 + j + 64] = __float2half((w0 * t1.y + w1 * t1.x) * sc);
            } else {
                sh[ho + cl * 128 + r0]       = __float2half(v0);
                sh[ho + (cl + 1) * 128 + r0] = __float2half(v1);
                sh[ho + cl * 128 + r1]       = __float2half(w0);
                sh[ho + (cl + 1) * 128 + r1] = __float2half(w1);
            }
        }
    }
    __syncthreads();

    if (seg < 2) {
        __half* Dst = (seg == 0) ? g_qh : g_kh;
        for (int i = tid; i < 4096; i += 256) {
            const int hsel = i >> 11;
            const int rem = i & 2047;
            const int row = rem >> 4, q = rem & 15;
            const size_t eo = ((size_t)((bidx * 16 + head0 + hsel) * 2048 + s_base + row)) * 128 + q * 8;
            *(uint4*)(Dst + eo) = *(const uint4*)(sh + hsel * 16384 + row * 128 + q * 8);
        }
    } else {
        for (int i = tid; i < 4096; i += 256) {
            const int hsel = i >> 11;
            const int rem = i & 2047;
            const int d = rem >> 4, q = rem & 15;
            const size_t eo = ((size_t)((bidx * 16 + head0 + hsel) * 128 + d)) * 2048 + s_base + q * 8;
            *(uint4*)(g_vth + eo) = *(const uint4*)(sh + hsel * 16384 + d * 128 + q * 8);
        }
    }
}

// ================= Wo GEMM: 128x256 pure fp16 =================
__global__ __launch_bounds__(256) void gemm_wo(
    const __half* __restrict__ Ah, const __half* __restrict__ Bh,
    const float* __restrict__ bias, float* __restrict__ C)
{
    extern __shared__ char smem[];
    const int tid = threadIdx.x;
    const int lane = tid & 31;
    const int wid = tid >> 5;
    const int wm = wid & 1;
    const int wn = wid >> 1;
    const int bm = blockIdx.y * 128;
    const int bn = blockIdx.x * 256;

    FP16_MAINLOOP256(Ah, Bh)

    const int rbase = bm + wm * 64 + (lane >> 2);
    const int cbase = bn + wn * 64 + (lane & 3) * 2;
#pragma unroll
    for (int mi = 0; mi < 4; mi++) {
#pragma unroll
        for (int ni = 0; ni < 8; ni++) {
            const int col = cbase + ni * 8;
            const float2 bv = *(const float2*)(bias + col);
            const int r0 = rbase + mi * 16;
            float2 o0, o1;
            o0.x = acc[mi][ni][0] + bv.x; o0.y = acc[mi][ni][1] + bv.y;
            o1.x = acc[mi][ni][2] + bv.x; o1.y = acc[mi][ni][3] + bv.y;
            *(float2*)(C + (size_t)r0 * 2048 + col) = o0;
            *(float2*)(C + (size_t)(r0 + 8) * 2048 + col) = o1;
        }
    }
}

// ================= flash attention: 64 q/CTA, 64-key chunks, 3 CTAs/SM =================
// K stage s: s*17408 (64 rows x 272B). V stage s: 34816 + s*18432 (128 rows x 144B).
#define AT_ROW   272
#define AT_VROW  144
#define AT_SMEM  71680

__global__ __launch_bounds__(128, 3) void attn_tc()
{
    extern __shared__ char sm[];
    const uint32_t sb = smem_u32(sm);
    const int tid = threadIdx.x;
    const int lane = tid & 31;
    const int w = tid >> 5;
    const int qb = blockIdx.x;
    const int bh = blockIdx.y;

    const size_t hbase = (size_t)bh * 2048 * 128;
    const uint4* Qh = (const uint4*)(g_qh + hbase + (size_t)qb * 64 * 128);
    const __half* Khp = g_kh + hbase;
    const __half* Vth = g_vth + (size_t)bh * 128 * 2048;

    // stage Q (64 rows x 272B = 17408 B) in K stage-0 region
    for (int i = tid; i < 1024; i += 128) {
        const uint32_t off = (uint32_t)((i >> 4) * AT_ROW + (i & 15) * 16);
        *(uint4*)(sm + off) = Qh[i];
    }
    __syncthreads();

    const uint32_t aOff = (uint32_t)((w * 16 + (lane & 15)) * AT_ROW + ((lane >> 4) << 4));
    uint32_t qfh[8][4];
#pragma unroll
    for (int kk = 0; kk < 8; kk++)
        ldsm4(qfh[kk], sb + aOff + kk * 32);
    __syncthreads();

    const uint32_t bOff = (uint32_t)(((lane & 7) + ((lane >> 4) << 3)) * AT_ROW
                                     + (((lane >> 3) & 1) << 4));
    const uint32_t bV   = (uint32_t)(((lane & 7) + ((lane >> 4) << 3)) * AT_VROW
                                     + (((lane >> 3) & 1) << 4));

    float O[16][4];
#pragma unroll
    for (int i = 0; i < 16; i++)
#pragma unroll
        for (int j = 0; j < 4; j++) O[i][j] = 0.0f;
    float m0 = -30000.0f, m1 = -30000.0f, l0 = 0.0f, l1 = 0.0f;
    const int g = lane >> 2, lam = lane & 3;

    auto load_chunk = [&](int kc, int st) {
        const uint32_t kbase = sb + (uint32_t)(st * 17408);
        const uint32_t vbase = sb + 34816u + (uint32_t)(st * 18432);
#pragma unroll
        for (int t = 0; t < 8; t++) {
            const int i = tid + t * 128;            // 0..1023
            const int kr = i >> 4, kq = i & 15;     // K: 64 rows x 16 uint4
            cp16(kbase + kr * AT_ROW + kq * 16, Khp + (size_t)(kc + kr) * 128 + kq * 8);
            const int vr = i >> 3, vq = i & 7;      // V: 128 rows x 8 uint4
            cp16(vbase + vr * AT_VROW + vq * 16, Vth + (size_t)vr * 2048 + kc + vq * 8);
        }
    };

    load_chunk(0, 0);
    CP_COMMIT();

    for (int cidx = 0; cidx < 32; cidx++) {
        CP_WAIT0();
        __syncthreads();
        if (cidx + 1 < 32) {
            load_chunk((cidx + 1) * 64, (cidx + 1) & 1);
            CP_COMMIT();
        }
        const uint32_t kst = sb + (uint32_t)((cidx & 1) * 17408);
        const uint32_t vst = sb + 34816u + (uint32_t)((cidx & 1) * 18432);

        // ---- S = Qh @ Kh^T (64 keys) ----
        float S[8][4];
#pragma unroll
        for (int t = 0; t < 8; t++)
#pragma unroll
            for (int j = 0; j < 4; j++) S[t][j] = 0.0f;

#pragma unroll
        for (int kk = 0; kk < 8; kk++) {
#pragma unroll
            for (int kg = 0; kg < 4; kg++) {
                uint32_t kbh[4];
                ldsm4(kbh, kst + bOff + kg * (16 * AT_ROW) + kk * 32);
                mma16816(S[2 * kg],     qfh[kk], kbh + 0);
                mma16816(S[2 * kg + 1], qfh[kk], kbh + 2);
            }
        }

        // ---- online softmax ----
        float mx0 = -30000.0f, mx1 = -30000.0f;
#pragma unroll
        for (int t = 0; t < 8; t++) {
            mx0 = fmaxf(mx0, fmaxf(S[t][0], S[t][1]));
            mx1 = fmaxf(mx1, fmaxf(S[t][2], S[t][3]));
        }
        mx0 = fmaxf(mx0, __shfl_xor_sync(0xffffffff, mx0, 1));
        mx0 = fmaxf(mx0, __shfl_xor_sync(0xffffffff, mx0, 2));
        mx1 = fmaxf(mx1, __shfl_xor_sync(0xffffffff, mx1, 1));
        mx1 = fmaxf(mx1, __shfl_xor_sync(0xffffffff, mx1, 2));

        const float nm0 = fmaxf(m0, mx0);
        const float nm1 = fmaxf(m1, mx1);
        const float al0 = __expf(fminf(m0 - nm0, 0.0f));
        const float al1 = __expf(fminf(m1 - nm1, 0.0f));
        m0 = nm0; m1 = nm1;

        float s0 = 0.0f, s1 = 0.0f;
#pragma unroll
        for (int t = 0; t < 8; t++) {
            S[t][0] = __expf(fminf(S[t][0] - m0, 0.0f));
            S[t][1] = __expf(fminf(S[t][1] - m0, 0.0f));
            S[t][2] = __expf(fminf(S[t][2] - m1, 0.0f));
            S[t][3] = __expf(fminf(S[t][3] - m1, 0.0f));
            s0 += S[t][0] + S[t][1];
            s1 += S[t][2] + S[t][3];
        }
        l0 = l0 * al0 + s0;
        l1 = l1 * al1 + s1;
        // warp-uniform rescale skip: once the running max is stable, alpha == 1 exactly
        if (!__all_sync(0xffffffff, (al0 == 1.0f) && (al1 == 1.0f))) {
#pragma unroll
            for (int nt = 0; nt < 16; nt++) {
                O[nt][0] *= al0; O[nt][1] *= al0;
                O[nt][2] *= al1; O[nt][3] *= al1;
            }
        }

        // ---- O += Ph @ Vh (4 x 16-key steps) ----
#pragma unroll
        for (int kt = 0; kt < 4; kt++) {
            uint32_t ph[4];
            ph[0] = h2_bits(__floats2half2_rn(S[2 * kt][0],     S[2 * kt][1]));
            ph[1] = h2_bits(__floats2half2_rn(S[2 * kt][2],     S[2 * kt][3]));
            ph[2] = h2_bits(__floats2half2_rn(S[2 * kt + 1][0], S[2 * kt + 1][1]));
            ph[3] = h2_bits(__floats2half2_rn(S[2 * kt + 1][2], S[2 * kt + 1][3]));
#pragma unroll
            for (int j = 0; j < 8; j++) {
                uint32_t vbh[4];
                ldsm4(vbh, vst + bV + j * (16 * AT_VROW) + kt * 32);
                mma16816(O[2 * j],     ph, vbh + 0);
                mma16816(O[2 * j + 1], ph, vbh + 2);
            }
        }
    }

    // ---- epilogue ----
    l0 += __shfl_xor_sync(0xffffffff, l0, 1);
    l0 += __shfl_xor_sync(0xffffffff, l0, 2);
    l1 += __shfl_xor_sync(0xffffffff, l1, 1);
    l1 += __shfl_xor_sync(0xffffffff, l1, 2);
    const float inv0 = 1.0f / l0;
    const float inv1 = 1.0f / l1;

    const int bb = bh >> 4, hh2 = bh & 15;
    const int row0 = qb * 64 + w * 16 + g;
    const size_t base0 = (size_t)(bb * 2048 + row0) * 2048 + hh2 * 128 + lam * 2;
    const size_t base1 = base0 + (size_t)8 * 2048;

#pragma unroll
    for (int nt = 0; nt < 16; nt++) {
        *(uint32_t*)(g_att_h + base0 + nt * 8) =
            h2_bits(__floats2half2_rn(O[nt][0] * inv0, O[nt][1] * inv0));
        *(uint32_t*)(g_att_h + base1 + nt * 8) =
            h2_bits(__floats2half2_rn(O[nt][2] * inv1, O[nt][3] * inv1));
    }
}

// ================= launch =================
extern "C" void kernel_launch(void* const* d_in, const int* in_sizes, int n_in,
                              void* d_out, int out_size)
{
    const float* x    = (const float*)d_in[0];
    const float* Wqkv = (const float*)d_in[1];
    const float* bqkv = (const float*)d_in[2];
    const float* Wo   = (const float*)d_in[3];
    const float* bo   = (const float*)d_in[4];
    float* out = (float*)d_out;

    __half *xh, *ah, *wqh, *woh;
    cudaGetSymbolAddress((void**)&xh, g_x_h);
    cudaGetSymbolAddress((void**)&ah, g_att_h);
    cudaGetSymbolAddress((void**)&wqh, g_Wq_h);
    cudaGetSymbolAddress((void**)&woh, g_Wo_h);

    cudaFuncSetAttribute(gemm_qkv_rope, cudaFuncAttributeMaxDynamicSharedMemorySize, GQ_SMEM);
    cudaFuncSetAttribute(gemm_wo, cudaFuncAttributeMaxDynamicSharedMemorySize, GW_SMEM);
    cudaFuncSetAttribute(attn_tc, cudaFuncAttributeMaxDynamicSharedMemorySize, AT_SMEM);

    // prep
    rope_table_kernel<<<(2048 * 64) / 256, 256>>>();
    convert_h<<<(4096 * 2048) / 256, 256>>>(x, xh, 4096 * 2048);
    transpose_h<<<dim3(6144 / 32, 2048 / 32), dim3(32, 8)>>>(Wqkv, wqh, 2048, 6144);
    transpose_h<<<dim3(2048 / 32, 2048 / 32), dim3(32, 8)>>>(Wo, woh, 2048, 2048);

    // 1) QKV projection + fused RoPE/head-split/V-transpose (128x256 tiles)
    gemm_qkv_rope<<<dim3(24, 32), 256, GQ_SMEM>>>(xh, wqh, bqkv);

    // 2) Tensor-core flash attention (64-key chunks)
    attn_tc<<<dim3(32, 32), 128, AT_SMEM>>>();

    // 3) Output projection (128x256 tiles)
    gemm_wo<<<dim3(8, 32), 256, GW_SMEM>>>(ah, woh, bo, out);
}